// round 14
// baseline (speedup 1.0000x reference)
#include <cuda_runtime.h>
#include <cuda_fp16.h>
#include <math.h>
#include <stdint.h>

#define NNODES 50000
#define HID 256
#define EMB 128
#define FIN 64
#define EMAX 800000
#define PB 120
#define SCAN_B 196
#define NB_M 391  // ceil(50000/128)

#define XN (NNODES * FIN)
#define WT2_OFF 16384
#define WTC_OFF (16384 + 65536)
#define WT_TOTAL (WTC_OFF + 3 * 65536)

// ---- scratch (static device globals: no allocation allowed) ----
__device__ __half g_hh[NNODES * HID];   // node features (ping)
__device__ __half g_t1[NNODES * HID];   // encoder intermediate / pong
__device__ __half g_gh[NNODES * HID];   // per-layer g = dinv*(h@W)
__device__ __half g_xh[XN];             // x in fp16
__device__ __half g_wt[WT_TOTAL];       // transposed fp16 weights [N][K]
__device__ float g_dinv[NNODES];
__device__ float g_psum[PB * HID];
__device__ float g_pmax[PB * HID];
__device__ float g_prob;
__device__ int g_src[EMAX];
__device__ int g_dst[EMAX];
__device__ int g_cnt[NNODES];
__device__ int g_cursor[NNODES];
__device__ int g_off[NNODES + 1];
__device__ int g_adj[EMAX];
__device__ int g_bsum[SCAN_B];
__device__ int g_flag;

// ---------------- helpers ----------------
__device__ __forceinline__ uint32_t smem_u32(const void* p) {
    uint32_t a;
    asm("{ .reg .u64 t; cvta.to.shared.u64 t, %1; cvt.u32.u64 %0, t; }" : "=r"(a) : "l"(p));
    return a;
}

__device__ __forceinline__ void cp_async16(void* smem_dst, const void* gsrc, bool pred) {
    uint32_t s = (uint32_t)__cvta_generic_to_shared(smem_dst);
    int sz = pred ? 16 : 0;
    asm volatile("cp.async.cg.shared.global [%0], [%1], 16, %2;\n" :: "r"(s), "l"(gsrc), "r"(sz));
}

__device__ __forceinline__ void ldm_x4(uint32_t& r0, uint32_t& r1, uint32_t& r2, uint32_t& r3,
                                       uint32_t addr) {
    asm volatile("ldmatrix.sync.aligned.m8n8.x4.shared.b16 {%0,%1,%2,%3}, [%4];"
                 : "=r"(r0), "=r"(r1), "=r"(r2), "=r"(r3) : "r"(addr));
}

// ---------------- setup kernels ----------------
__global__ void init_k(int* flag, int* cnt, int* cursor) {
    int i = blockIdx.x * blockDim.x + threadIdx.x;
    if (i == 0) *flag = 1;
    if (i < NNODES) { cnt[i] = 0; cursor[i] = 0; }
}

// prep: xh = fp16(x); wt = fp16(transpose(W1,W2,convW)) into [N,K] K-major
__global__ void prep_k(const float* __restrict__ x, const float* __restrict__ W1,
                       const float* __restrict__ W2, const float* __restrict__ convW,
                       __half* __restrict__ xh, __half* __restrict__ wt) {
    int i = blockIdx.x * blockDim.x + threadIdx.x;
    if (i < XN) { xh[i] = __float2half_rn(x[i]); return; }
    int j = i - XN;
    if (j < 16384) {  // Wt1[n][k], k<64
        int n = j >> 6, k = j & 63;
        wt[j] = __float2half_rn(W1[k * 256 + n]);
        return;
    }
    j -= 16384;
    if (j < 65536) {  // Wt2[n][k]
        int n = j >> 8, k = j & 255;
        wt[WT2_OFF + j] = __float2half_rn(W2[k * 256 + n]);
        return;
    }
    j -= 65536;
    if (j < 3 * 65536) {
        int l = j >> 16;
        int r = j & 65535;
        int n = r >> 8, k = r & 255;
        wt[WTC_OFF + j] = __float2half_rn(convW[l * 65536 + k * 256 + n]);
    }
}

__global__ void detect_k(const int* p, int* flag) {
    int i = blockIdx.x * blockDim.x + threadIdx.x;
    if (p[2 * i + 1] != 0) *flag = 0;
}

__global__ void convert_edges_k(const void* ei, const int* flag, int* src, int* dst,
                                int* cnt, int E) {
    int i = blockIdx.x * blockDim.x + threadIdx.x;
    if (i >= E) return;
    int s, d;
    if (*flag) {
        const long long* p = (const long long*)ei;
        s = (int)p[i];
        d = (int)p[E + i];
    } else {
        const int* p = (const int*)ei;
        s = p[i];
        d = p[E + i];
    }
    src[i] = s;
    dst[i] = d;
    atomicAdd(&cnt[d], 1);
}

__global__ void scanA_k(const int* __restrict__ cnt, int* __restrict__ bsum,
                        float* __restrict__ dinv) {
    __shared__ int s[256];
    int t = threadIdx.x;
    int i = blockIdx.x * 256 + t;
    int v = (i < NNODES) ? cnt[i] : 0;
    if (i < NNODES) dinv[i] = rsqrtf((float)v + 1.0f);
    s[t] = v;
    __syncthreads();
    for (int d = 128; d > 0; d >>= 1) {
        if (t < d) s[t] += s[t + d];
        __syncthreads();
    }
    if (t == 0) bsum[blockIdx.x] = s[0];
}

__global__ void scanB_k(const int* __restrict__ cnt, const int* __restrict__ bsum,
                        int* __restrict__ off) {
    __shared__ int s[256];
    __shared__ int red[256];
    int t = threadIdx.x;
    int b = blockIdx.x;
    int i = b * 256 + t;
    int val = (i < NNODES) ? cnt[i] : 0;
    int partial = 0;
    for (int j = t; j < b; j += 256) partial += bsum[j];
    red[t] = partial;
    __syncthreads();
    for (int d = 128; d > 0; d >>= 1) {
        if (t < d) red[t] += red[t + d];
        __syncthreads();
    }
    int base = red[0];
    s[t] = val;
    __syncthreads();
    for (int d = 1; d < 256; d <<= 1) {
        int tmp = (t >= d) ? s[t - d] : 0;
        __syncthreads();
        s[t] += tmp;
        __syncthreads();
    }
    if (i <= NNODES) off[i] = base + s[t] - val;
}

__global__ void fill_k(const int* __restrict__ src, const int* __restrict__ dst,
                       const int* __restrict__ off, int* __restrict__ cursor,
                       int* __restrict__ adj, int E) {
    int i = blockIdx.x * blockDim.x + threadIdx.x;
    if (i >= E) return;
    int d = dst[i];
    int p = atomicAdd(&cursor[d], 1);
    adj[off[d] + p] = src[i];
}

// ---------------- FP16 tensor-core GEMM (mma.m16n8k16 + ldmatrix) ----------------
// bn = bn0 + 128*blockIdx.y, so the same kernel serves full (grid.y=2) and
// half-column (grid.y=1, bn0 in {0,128}) launches.
#define TILE_BYTES 16384                 // 128 x 128B
#define STAGE_BYTES (2 * TILE_BYTES)     // A + B
#define NSTAGE 3
#define GEMM_SMEM (NSTAGE * STAGE_BYTES) // 98304

__global__ __launch_bounds__(256, 2) void gemm_h_k(
    const __half* __restrict__ A, const __half* __restrict__ Bt,
    const float* __restrict__ bias, __half* __restrict__ Cout,
    const float* __restrict__ dinvv, int M, int K, int relu_flag, int bn0) {
    extern __shared__ char smem[];
    uint32_t sb = smem_u32(smem);

    int tid = threadIdx.x;
    int warp = tid >> 5;
    int lane = tid & 31;
    int grp = lane >> 2;
    int tig = lane & 3;
    int wm = warp >> 1;
    int wn = warp & 1;
    int bm = blockIdx.x * 128;
    int bn = bn0 + blockIdx.y * 128;
    int ntiles = K >> 6;

    float c[2][8][4];
#pragma unroll
    for (int mt = 0; mt < 2; mt++)
#pragma unroll
        for (int nt = 0; nt < 8; nt++)
#pragma unroll
            for (int q = 0; q < 4; q++) c[mt][nt][q] = 0.0f;

    auto stage = [&](int t) {
        char* As = smem + (t % NSTAGE) * STAGE_BYTES;
        char* Bs = As + TILE_BYTES;
        int k0 = t << 6;
#pragma unroll
        for (int i = 0; i < 4; i++) {
            int ci = tid + i * 256;
            int row = ci >> 3;
            int ch = ci & 7;
            uint32_t sw = (uint32_t)(row * 128 + ((ch ^ (row & 7)) << 4));
            int gm = bm + row;
            bool ok = gm < M;
            int gms = ok ? gm : 0;
            cp_async16(As + sw, A + (size_t)gms * K + k0 + ch * 8, ok);
            cp_async16(Bs + sw, Bt + (size_t)(bn + row) * K + k0 + ch * 8, true);
        }
        asm volatile("cp.async.commit_group;\n");
    };

    stage(0);
    if (ntiles > 1) stage(1);

    for (int t = 0; t < ntiles; t++) {
        int commits = (ntiles < t + 2) ? ntiles : (t + 2);
        int pend = commits - t - 1;
        if (pend >= 1) asm volatile("cp.async.wait_group 1;\n");
        else asm volatile("cp.async.wait_group 0;\n");
        __syncthreads();
        if (t + 2 < ntiles) stage(t + 2);

        uint32_t as_b = sb + (t % NSTAGE) * STAGE_BYTES;
        uint32_t bs_b = as_b + TILE_BYTES;

#pragma unroll
        for (int ks = 0; ks < 4; ks++) {
            int kc0 = ks << 1;
            uint32_t a[2][4];
#pragma unroll
            for (int mt = 0; mt < 2; mt++) {
                int row = wm * 32 + mt * 16 + (lane & 7) + (lane & 8);
                int ch = kc0 + (lane >> 4);
                uint32_t addr = as_b + (uint32_t)(row * 128 + ((ch ^ (row & 7)) << 4));
                ldm_x4(a[mt][0], a[mt][1], a[mt][2], a[mt][3], addr);
            }
            uint32_t b[8][2];
#pragma unroll
            for (int p = 0; p < 4; p++) {
                int nrow = wn * 64 + p * 16 + (lane & 7) + ((lane & 16) >> 1);
                int ch = kc0 + ((lane >> 3) & 1);
                uint32_t addr = bs_b + (uint32_t)(nrow * 128 + ((ch ^ (nrow & 7)) << 4));
                uint32_t r0, r1, r2, r3;
                ldm_x4(r0, r1, r2, r3, addr);
                b[2 * p][0] = r0; b[2 * p][1] = r1;
                b[2 * p + 1][0] = r2; b[2 * p + 1][1] = r3;
            }
#pragma unroll
            for (int mt = 0; mt < 2; mt++)
#pragma unroll
                for (int nt = 0; nt < 8; nt++) {
                    asm volatile(
                        "mma.sync.aligned.m16n8k16.row.col.f32.f16.f16.f32 "
                        "{%0,%1,%2,%3},{%4,%5,%6,%7},{%8,%9},{%0,%1,%2,%3};\n"
                        : "+f"(c[mt][nt][0]), "+f"(c[mt][nt][1]),
                          "+f"(c[mt][nt][2]), "+f"(c[mt][nt][3])
                        : "r"(a[mt][0]), "r"(a[mt][1]), "r"(a[mt][2]), "r"(a[mt][3]),
                          "r"(b[nt][0]), "r"(b[nt][1]));
                }
        }
    }

    // epilogue
#pragma unroll
    for (int mt = 0; mt < 2; mt++) {
        int r0 = bm + wm * 32 + mt * 16 + grp;
        int r1 = r0 + 8;
        float d0 = 1.0f, d1 = 1.0f;
        if (dinvv) {
            if (r0 < M) d0 = dinvv[r0];
            if (r1 < M) d1 = dinvv[r1];
        }
#pragma unroll
        for (int nt = 0; nt < 8; nt++) {
            int col = bn + wn * 64 + nt * 8 + 2 * tig;
            float b0f = 0.f, b1f = 0.f;
            if (bias) { b0f = bias[col]; b1f = bias[col + 1]; }
            float v0 = c[mt][nt][0] + b0f;
            float v1 = c[mt][nt][1] + b1f;
            float v2 = c[mt][nt][2] + b0f;
            float v3 = c[mt][nt][3] + b1f;
            if (relu_flag) {
                v0 = fmaxf(v0, 0.f); v1 = fmaxf(v1, 0.f);
                v2 = fmaxf(v2, 0.f); v3 = fmaxf(v3, 0.f);
            }
            v0 *= d0; v1 *= d0; v2 *= d1; v3 *= d1;
            if (r0 < M) *(__half2*)(Cout + (size_t)r0 * 256 + col) = __floats2half2_rn(v0, v1);
            if (r1 < M) *(__half2*)(Cout + (size_t)r1 * 256 + col) = __floats2half2_rn(v2, v3);
        }
    }
}

// ---------------- CSR aggregate over a 128-column half ----------------
// One warp per node; lane owns 4 cols (uint2 = 8B per gather; 256B/row coalesced).
__device__ __forceinline__ void acc_add2(float* acc, uint2 v) {
    const __half2* p = (const __half2*)&v;
#pragma unroll
    for (int q = 0; q < 2; q++) {
        float2 f = __half22float2(p[q]);
        acc[2 * q] += f.x;
        acc[2 * q + 1] += f.y;
    }
}

__global__ void aggregate_half_k(const int* __restrict__ off, const int* __restrict__ adj,
                                 const __half* __restrict__ g, const float* __restrict__ dinv,
                                 const float* __restrict__ bias, __half* __restrict__ h,
                                 int colbase) {
    int node = (blockIdx.x * blockDim.x + threadIdx.x) >> 5;
    if (node >= NNODES) return;
    int lane = threadIdx.x & 31;
    int col = colbase + (lane << 2);

    float acc[4];
    {
        uint2 v = *(const uint2*)(g + (size_t)node * HID + col);
        const __half2* p = (const __half2*)&v;
        float2 f0 = __half22float2(p[0]);
        float2 f1 = __half22float2(p[1]);
        acc[0] = f0.x; acc[1] = f0.y; acc[2] = f1.x; acc[3] = f1.y;
    }
    int e0 = off[node], e1 = off[node + 1];
    int j = e0;
    for (; j + 4 <= e1; j += 4) {
        int s0 = adj[j], s1 = adj[j + 1], s2 = adj[j + 2], s3 = adj[j + 3];
        uint2 v0 = *(const uint2*)(g + (size_t)s0 * HID + col);
        uint2 v1 = *(const uint2*)(g + (size_t)s1 * HID + col);
        uint2 v2 = *(const uint2*)(g + (size_t)s2 * HID + col);
        uint2 v3 = *(const uint2*)(g + (size_t)s3 * HID + col);
        acc_add2(acc, v0);
        acc_add2(acc, v1);
        acc_add2(acc, v2);
        acc_add2(acc, v3);
    }
    for (; j < e1; j++) {
        int s = adj[j];
        uint2 v = *(const uint2*)(g + (size_t)s * HID + col);
        acc_add2(acc, v);
    }
    float dvv = dinv[node];
    float o0 = fmaxf(fmaf(acc[0], dvv, bias[col + 0]), 0.0f);
    float o1 = fmaxf(fmaf(acc[1], dvv, bias[col + 1]), 0.0f);
    float o2 = fmaxf(fmaf(acc[2], dvv, bias[col + 2]), 0.0f);
    float o3 = fmaxf(fmaf(acc[3], dvv, bias[col + 3]), 0.0f);
    __half2 h0 = __floats2half2_rn(o0, o1);
    __half2 h1 = __floats2half2_rn(o2, o3);
    uint2 out;
    out.x = *(uint32_t*)&h0;
    out.y = *(uint32_t*)&h1;
    *(uint2*)(h + (size_t)node * HID + col) = out;
}

// ---------------- pooling + head + output ----------------
__global__ void pool_partial_k(const __half* __restrict__ h, float* __restrict__ psum,
                               float* __restrict__ pmax) {
    int col = threadIdx.x;
    int b = blockIdx.x;
    float s = 0.0f, m = -1e30f;
    for (int r = b; r < NNODES; r += PB) {
        float v = __half2float(h[(size_t)r * HID + col]);
        s += v;
        m = fmaxf(m, v);
    }
    psum[b * HID + col] = s;
    pmax[b * HID + col] = m;
}

__global__ void head_k(const float* __restrict__ psum, const float* __restrict__ pmax,
                       const float* __restrict__ Wg1, const float* __restrict__ bg1,
                       const float* __restrict__ Wg2, const float* __restrict__ bg2,
                       const float* __restrict__ Wd1, const float* __restrict__ bd1,
                       const float* __restrict__ Wd2, const float* __restrict__ bd2,
                       float* __restrict__ out, float* __restrict__ prob) {
    __shared__ float rep[2 * HID];
    __shared__ float u1[HID];
    __shared__ float ge[EMB];
    __shared__ float v1[HID];
    __shared__ float vv[HID];
    __shared__ float red[HID];
    int t = threadIdx.x;

    if (t < HID) {
        float s = 0.0f;
        for (int i = 0; i < PB; i++) s += psum[i * HID + t];
        rep[t] = s * (1.0f / NNODES);
    } else {
        int c = t - HID;
        float m = -1e30f;
        for (int i = 0; i < PB; i++) m = fmaxf(m, pmax[i * HID + c]);
        rep[HID + c] = m;
    }
    __syncthreads();

    if (t < HID) {
        float s = bg1[t];
        for (int k = 0; k < 2 * HID; k++) s += rep[k] * Wg1[k * HID + t];
        u1[t] = fmaxf(s, 0.0f);
    }
    __syncthreads();

    if (t < EMB) {
        float s = bg2[t];
        for (int k = 0; k < HID; k++) s += u1[k] * Wg2[k * EMB + t];
        ge[t] = s;
        out[t] = s;
    }
    __syncthreads();

    if (t < HID) {
        float s = bd1[t];
        for (int k = 0; k < EMB; k++) s += ge[k] * Wd1[k * HID + t];
        v1[t] = fmaxf(s, 0.0f);
    }
    __syncthreads();

    if (t < HID) {
        float s = bd2[t];
        for (int k = 0; k < HID; k++) s += v1[k] * Wd2[k * HID + t];
        vv[t] = s;
    }
    __syncthreads();

    if (t < HID) red[t] = vv[t] * vv[t];
    __syncthreads();
    for (int s = HID / 2; s > 0; s >>= 1) {
        if (t < s) red[t] += red[t + s];
        __syncthreads();
    }
    if (t == 0) *prob = 1.0f / (1.0f + expf(-red[0]));
}

__global__ void fill_probs_k(float* __restrict__ out, const float* __restrict__ prob, int E) {
    int i = blockIdx.x * blockDim.x + threadIdx.x;
    float p = *prob;
    int base = i << 2;
    if (base + 3 < E) {
        *(float4*)(out + EMB + base) = make_float4(p, p, p, p);
    } else {
        for (int j = base; j < E; j++) out[EMB + j] = p;
    }
}

// ---------------- launch ----------------
extern "C" void kernel_launch(void* const* d_in, const int* in_sizes, int n_in,
                              void* d_out, int out_size) {
    const float* x = (const float*)d_in[0];
    const void* ei = d_in[1];
    const float* W1 = (const float*)d_in[2];
    const float* b1 = (const float*)d_in[3];
    const float* W2 = (const float*)d_in[4];
    const float* b2 = (const float*)d_in[5];
    const float* convW = (const float*)d_in[6];
    const float* convb = (const float*)d_in[7];
    const float* Wg1 = (const float*)d_in[8];
    const float* bg1 = (const float*)d_in[9];
    const float* Wg2 = (const float*)d_in[10];
    const float* bg2 = (const float*)d_in[11];
    const float* Wd1 = (const float*)d_in[12];
    const float* bd1 = (const float*)d_in[13];
    const float* Wd2 = (const float*)d_in[14];
    const float* bd2 = (const float*)d_in[15];

    int E = in_sizes[1] / 2;

    float *dinv, *psum, *pmax, *prob;
    __half *hh, *t1, *gh, *xh, *wt;
    int *src, *dst, *cnt, *cursor, *off, *adj, *bsum, *flag;
    cudaGetSymbolAddress((void**)&hh, g_hh);
    cudaGetSymbolAddress((void**)&t1, g_t1);
    cudaGetSymbolAddress((void**)&gh, g_gh);
    cudaGetSymbolAddress((void**)&xh, g_xh);
    cudaGetSymbolAddress((void**)&wt, g_wt);
    cudaGetSymbolAddress((void**)&dinv, g_dinv);
    cudaGetSymbolAddress((void**)&psum, g_psum);
    cudaGetSymbolAddress((void**)&pmax, g_pmax);
    cudaGetSymbolAddress((void**)&prob, g_prob);
    cudaGetSymbolAddress((void**)&src, g_src);
    cudaGetSymbolAddress((void**)&dst, g_dst);
    cudaGetSymbolAddress((void**)&cnt, g_cnt);
    cudaGetSymbolAddress((void**)&cursor, g_cursor);
    cudaGetSymbolAddress((void**)&off, g_off);
    cudaGetSymbolAddress((void**)&adj, g_adj);
    cudaGetSymbolAddress((void**)&bsum, g_bsum);
    cudaGetSymbolAddress((void**)&flag, g_flag);

    cudaFuncSetAttribute(gemm_h_k, cudaFuncAttributeMaxDynamicSharedMemorySize, GEMM_SMEM);

    dim3 gfull(NB_M, 2);
    dim3 ghalf(NB_M, 1);
    int prep_blocks = (XN + WT_TOTAL + 255) / 256;
    int agg_blocks = 6250;  // NNODES*32/256 exactly

    // Handles intentionally leaked (destroying a capture-state stream is an error;
    // kernel_launch runs only a handful of times; no tracked device memory held).
    cudaStream_t s2;
    cudaStreamCreateWithFlags(&s2, cudaStreamNonBlocking);
    cudaEvent_t evF, evJ, eA[3], eD[3];
    cudaEventCreateWithFlags(&evF, cudaEventDisableTiming);
    cudaEventCreateWithFlags(&evJ, cudaEventDisableTiming);
    for (int l = 0; l < 3; l++) {
        cudaEventCreateWithFlags(&eA[l], cudaEventDisableTiming);
        cudaEventCreateWithFlags(&eD[l], cudaEventDisableTiming);
    }

    cudaEventRecord(evF, 0);
    cudaStreamWaitEvent(s2, evF, 0);

    // Branch B (s2): CSR build
    init_k<<<(NNODES + 255) / 256, 256, 0, s2>>>(flag, cnt, cursor);
    detect_k<<<16, 256, 0, s2>>>((const int*)ei, flag);
    convert_edges_k<<<(E + 255) / 256, 256, 0, s2>>>(ei, flag, src, dst, cnt, E);
    scanA_k<<<SCAN_B, 256, 0, s2>>>(cnt, bsum, dinv);
    scanB_k<<<SCAN_B, 256, 0, s2>>>(cnt, bsum, off);
    fill_k<<<(E + 255) / 256, 256, 0, s2>>>(src, dst, off, cursor, adj, E);
    cudaEventRecord(evJ, s2);

    // Branch A (main): prep + encoder GEMMs
    prep_k<<<prep_blocks, 256>>>(x, W1, W2, convW, xh, wt);
    gemm_h_k<<<gfull, 256, GEMM_SMEM>>>(xh, wt, b1, t1, nullptr, NNODES, FIN, 1, 0);
    gemm_h_k<<<gfull, 256, GEMM_SMEM>>>(t1, wt + WT2_OFF, b2, hh, nullptr, NNODES, HID, 0, 0);

    // Join: conv layers need dinv/off/adj (B) and hh (A)
    cudaStreamWaitEvent(0, evJ, 0);

    // GCN layers, software-pipelined across column halves with ping-pong h:
    //   G0(main) -> [A0(main) || G1(s2)] -> A1(s2); next layer waits eD.
    __half* hin = hh;
    __half* hout = t1;
    for (int l = 0; l < 3; l++) {
        const __half* wl = wt + WTC_OFF + l * 65536;
        const float* bl = convb + (size_t)l * HID;
        gemm_h_k<<<ghalf, 256, GEMM_SMEM>>>(hin, wl, nullptr, gh, dinv, NNODES, HID, 0, 0);
        cudaEventRecord(eA[l], 0);
        aggregate_half_k<<<agg_blocks, 256>>>(off, adj, gh, dinv, bl, hout, 0);
        cudaStreamWaitEvent(s2, eA[l], 0);
        gemm_h_k<<<ghalf, 256, GEMM_SMEM, s2>>>(hin, wl, nullptr, gh, dinv, NNODES, HID, 0, 128);
        aggregate_half_k<<<agg_blocks, 256, 0, s2>>>(off, adj, gh, dinv, bl, hout, 128);
        cudaEventRecord(eD[l], s2);
        cudaStreamWaitEvent(0, eD[l], 0);
        __half* tmp = hin; hin = hout; hout = tmp;
    }

    // pooling + head + output (final h is in hin after 3 swaps)
    pool_partial_k<<<PB, 256>>>(hin, psum, pmax);
    head_k<<<1, 512>>>(psum, pmax, Wg1, bg1, Wg2, bg2, Wd1, bd1, Wd2, bd2, (float*)d_out, prob);
    fill_probs_k<<<(E / 4 + 255) / 256, 256>>>((float*)d_out, prob, E);
}

// round 15
// speedup vs baseline: 1.0624x; 1.0624x over previous
#include <cuda_runtime.h>
#include <cuda_fp16.h>
#include <math.h>
#include <stdint.h>

#define NNODES 50000
#define HID 256
#define EMB 128
#define FIN 64
#define EMAX 800000
#define PB 120
#define SCAN_B 196
#define NB_M 391  // ceil(50000/128)

#define XN (NNODES * FIN)
#define WT2_OFF 16384
#define WTC_OFF (16384 + 65536)
#define WT_TOTAL (WTC_OFF + 3 * 65536)

// ---- scratch (static device globals: no allocation allowed) ----
__device__ __half g_hh[NNODES * HID];   // node features (fp16)
__device__ __half g_t1[NNODES * HID];   // encoder intermediate
__device__ __half g_gh[NNODES * HID];   // per-layer g = dinv*(h@W)
__device__ __half g_xh[XN];             // x in fp16
__device__ __half g_wt[WT_TOTAL];       // transposed fp16 weights [N][K]
__device__ float g_dinv[NNODES];
__device__ float g_psum[PB * HID];
__device__ float g_pmax[PB * HID];
__device__ float g_prob;
__device__ int g_src[EMAX];
__device__ int g_dst[EMAX];
__device__ int g_cnt[NNODES];
__device__ int g_cursor[NNODES];
__device__ int g_off[NNODES + 1];
__device__ int g_adj[EMAX];
__device__ int g_bsum[SCAN_B];
__device__ int g_flag;

// ---------------- helpers ----------------
__device__ __forceinline__ uint32_t smem_u32(const void* p) {
    uint32_t a;
    asm("{ .reg .u64 t; cvta.to.shared.u64 t, %1; cvt.u32.u64 %0, t; }" : "=r"(a) : "l"(p));
    return a;
}

__device__ __forceinline__ void cp_async16(void* smem_dst, const void* gsrc, bool pred) {
    uint32_t s = (uint32_t)__cvta_generic_to_shared(smem_dst);
    int sz = pred ? 16 : 0;
    asm volatile("cp.async.cg.shared.global [%0], [%1], 16, %2;\n" :: "r"(s), "l"(gsrc), "r"(sz));
}

__device__ __forceinline__ void ldm_x4(uint32_t& r0, uint32_t& r1, uint32_t& r2, uint32_t& r3,
                                       uint32_t addr) {
    asm volatile("ldmatrix.sync.aligned.m8n8.x4.shared.b16 {%0,%1,%2,%3}, [%4];"
                 : "=r"(r0), "=r"(r1), "=r"(r2), "=r"(r3) : "r"(addr));
}

// ---------------- setup kernels ----------------
__global__ void init_k(int* flag, int* cnt, int* cursor) {
    int i = blockIdx.x * blockDim.x + threadIdx.x;
    if (i == 0) *flag = 1;
    if (i < NNODES) { cnt[i] = 0; cursor[i] = 0; }
}

// prep: xh = fp16(x); wt = fp16(transpose(W1,W2,convW)) into [N,K] K-major
__global__ void prep_k(const float* __restrict__ x, const float* __restrict__ W1,
                       const float* __restrict__ W2, const float* __restrict__ convW,
                       __half* __restrict__ xh, __half* __restrict__ wt) {
    int i = blockIdx.x * blockDim.x + threadIdx.x;
    if (i < XN) { xh[i] = __float2half_rn(x[i]); return; }
    int j = i - XN;
    if (j < 16384) {  // Wt1[n][k], k<64
        int n = j >> 6, k = j & 63;
        wt[j] = __float2half_rn(W1[k * 256 + n]);
        return;
    }
    j -= 16384;
    if (j < 65536) {  // Wt2[n][k]
        int n = j >> 8, k = j & 255;
        wt[WT2_OFF + j] = __float2half_rn(W2[k * 256 + n]);
        return;
    }
    j -= 65536;
    if (j < 3 * 65536) {
        int l = j >> 16;
        int r = j & 65535;
        int n = r >> 8, k = r & 255;
        wt[WTC_OFF + j] = __float2half_rn(convW[l * 65536 + k * 256 + n]);
    }
}

__global__ void detect_k(const int* p, int* flag) {
    int i = blockIdx.x * blockDim.x + threadIdx.x;
    if (p[2 * i + 1] != 0) *flag = 0;
}

__global__ void convert_edges_k(const void* ei, const int* flag, int* src, int* dst,
                                int* cnt, int E) {
    int i = blockIdx.x * blockDim.x + threadIdx.x;
    if (i >= E) return;
    int s, d;
    if (*flag) {
        const long long* p = (const long long*)ei;
        s = (int)p[i];
        d = (int)p[E + i];
    } else {
        const int* p = (const int*)ei;
        s = p[i];
        d = p[E + i];
    }
    src[i] = s;
    dst[i] = d;
    atomicAdd(&cnt[d], 1);
}

__global__ void scanA_k(const int* __restrict__ cnt, int* __restrict__ bsum,
                        float* __restrict__ dinv) {
    __shared__ int s[256];
    int t = threadIdx.x;
    int i = blockIdx.x * 256 + t;
    int v = (i < NNODES) ? cnt[i] : 0;
    if (i < NNODES) dinv[i] = rsqrtf((float)v + 1.0f);
    s[t] = v;
    __syncthreads();
    for (int d = 128; d > 0; d >>= 1) {
        if (t < d) s[t] += s[t + d];
        __syncthreads();
    }
    if (t == 0) bsum[blockIdx.x] = s[0];
}

__global__ void scanB_k(const int* __restrict__ cnt, const int* __restrict__ bsum,
                        int* __restrict__ off) {
    __shared__ int s[256];
    __shared__ int red[256];
    int t = threadIdx.x;
    int b = blockIdx.x;
    int i = b * 256 + t;
    int val = (i < NNODES) ? cnt[i] : 0;
    int partial = 0;
    for (int j = t; j < b; j += 256) partial += bsum[j];
    red[t] = partial;
    __syncthreads();
    for (int d = 128; d > 0; d >>= 1) {
        if (t < d) red[t] += red[t + d];
        __syncthreads();
    }
    int base = red[0];
    s[t] = val;
    __syncthreads();
    for (int d = 1; d < 256; d <<= 1) {
        int tmp = (t >= d) ? s[t - d] : 0;
        __syncthreads();
        s[t] += tmp;
        __syncthreads();
    }
    if (i <= NNODES) off[i] = base + s[t] - val;
}

__global__ void fill_k(const int* __restrict__ src, const int* __restrict__ dst,
                       const int* __restrict__ off, int* __restrict__ cursor,
                       int* __restrict__ adj, int E) {
    int i = blockIdx.x * blockDim.x + threadIdx.x;
    if (i >= E) return;
    int d = dst[i];
    int p = atomicAdd(&cursor[d], 1);
    adj[off[d] + p] = src[i];
}

// ---------------- FP16 tensor-core GEMM (mma.m16n8k16 + ldmatrix) ----------------
// Single __syncthreads per k-tile: stage(t+2) is issued AFTER the top barrier, so
// buffer (t+2)%3 (last read in iter t-1, before every warp passed this barrier) is free.
#define TILE_BYTES 16384                 // 128 x 128B
#define STAGE_BYTES (2 * TILE_BYTES)     // A + B
#define NSTAGE 3
#define GEMM_SMEM (NSTAGE * STAGE_BYTES) // 98304

__global__ __launch_bounds__(256, 2) void gemm_h_k(
    const __half* __restrict__ A, const __half* __restrict__ Bt,
    const float* __restrict__ bias, __half* __restrict__ Cout,
    const float* __restrict__ dinvv, int M, int K, int relu_flag) {
    extern __shared__ char smem[];
    uint32_t sb = smem_u32(smem);

    int tid = threadIdx.x;
    int warp = tid >> 5;
    int lane = tid & 31;
    int grp = lane >> 2;   // 0..7
    int tig = lane & 3;    // 0..3
    int wm = warp >> 1;    // 0..3 -> m offset wm*32
    int wn = warp & 1;     // 0..1 -> n offset wn*64
    int bm = blockIdx.x * 128;
    int bn = blockIdx.y * 128;
    int ntiles = K >> 6;

    float c[2][8][4];
#pragma unroll
    for (int mt = 0; mt < 2; mt++)
#pragma unroll
        for (int nt = 0; nt < 8; nt++)
#pragma unroll
            for (int q = 0; q < 4; q++) c[mt][nt][q] = 0.0f;

    auto stage = [&](int t) {
        char* As = smem + (t % NSTAGE) * STAGE_BYTES;
        char* Bs = As + TILE_BYTES;
        int k0 = t << 6;
#pragma unroll
        for (int i = 0; i < 4; i++) {
            int ci = tid + i * 256;   // 0..1023
            int row = ci >> 3;
            int ch = ci & 7;
            uint32_t sw = (uint32_t)(row * 128 + ((ch ^ (row & 7)) << 4));
            int gm = bm + row;
            bool ok = gm < M;
            int gms = ok ? gm : 0;
            cp_async16(As + sw, A + (size_t)gms * K + k0 + ch * 8, ok);
            cp_async16(Bs + sw, Bt + (size_t)(bn + row) * K + k0 + ch * 8, true);
        }
        asm volatile("cp.async.commit_group;\n");
    };

    stage(0);
    if (ntiles > 1) stage(1);

    for (int t = 0; t < ntiles; t++) {
        int commits = (ntiles < t + 2) ? ntiles : (t + 2);
        int pend = commits - t - 1;  // 0 or 1
        if (pend >= 1) asm volatile("cp.async.wait_group 1;\n");
        else asm volatile("cp.async.wait_group 0;\n");
        __syncthreads();
        if (t + 2 < ntiles) stage(t + 2);

        uint32_t as_b = sb + (t % NSTAGE) * STAGE_BYTES;
        uint32_t bs_b = as_b + TILE_BYTES;

#pragma unroll
        for (int ks = 0; ks < 4; ks++) {
            int kc0 = ks << 1;
            uint32_t a[2][4];
#pragma unroll
            for (int mt = 0; mt < 2; mt++) {
                int row = wm * 32 + mt * 16 + (lane & 7) + (lane & 8);
                int ch = kc0 + (lane >> 4);
                uint32_t addr = as_b + (uint32_t)(row * 128 + ((ch ^ (row & 7)) << 4));
                ldm_x4(a[mt][0], a[mt][1], a[mt][2], a[mt][3], addr);
            }
            uint32_t b[8][2];
#pragma unroll
            for (int p = 0; p < 4; p++) {
                int nrow = wn * 64 + p * 16 + (lane & 7) + ((lane & 16) >> 1);
                int ch = kc0 + ((lane >> 3) & 1);
                uint32_t addr = bs_b + (uint32_t)(nrow * 128 + ((ch ^ (nrow & 7)) << 4));
                uint32_t r0, r1, r2, r3;
                ldm_x4(r0, r1, r2, r3, addr);
                b[2 * p][0] = r0; b[2 * p][1] = r1;
                b[2 * p + 1][0] = r2; b[2 * p + 1][1] = r3;
            }
#pragma unroll
            for (int mt = 0; mt < 2; mt++)
#pragma unroll
                for (int nt = 0; nt < 8; nt++) {
                    asm volatile(
                        "mma.sync.aligned.m16n8k16.row.col.f32.f16.f16.f32 "
                        "{%0,%1,%2,%3},{%4,%5,%6,%7},{%8,%9},{%0,%1,%2,%3};\n"
                        : "+f"(c[mt][nt][0]), "+f"(c[mt][nt][1]),
                          "+f"(c[mt][nt][2]), "+f"(c[mt][nt][3])
                        : "r"(a[mt][0]), "r"(a[mt][1]), "r"(a[mt][2]), "r"(a[mt][3]),
                          "r"(b[nt][0]), "r"(b[nt][1]));
                }
        }
    }

    // epilogue
#pragma unroll
    for (int mt = 0; mt < 2; mt++) {
        int r0 = bm + wm * 32 + mt * 16 + grp;
        int r1 = r0 + 8;
        float d0 = 1.0f, d1 = 1.0f;
        if (dinvv) {
            if (r0 < M) d0 = dinvv[r0];
            if (r1 < M) d1 = dinvv[r1];
        }
#pragma unroll
        for (int nt = 0; nt < 8; nt++) {
            int col = bn + wn * 64 + nt * 8 + 2 * tig;
            float b0f = 0.f, b1f = 0.f;
            if (bias) { b0f = bias[col]; b1f = bias[col + 1]; }
            float v0 = c[mt][nt][0] + b0f;
            float v1 = c[mt][nt][1] + b1f;
            float v2 = c[mt][nt][2] + b0f;
            float v3 = c[mt][nt][3] + b1f;
            if (relu_flag) {
                v0 = fmaxf(v0, 0.f); v1 = fmaxf(v1, 0.f);
                v2 = fmaxf(v2, 0.f); v3 = fmaxf(v3, 0.f);
            }
            v0 *= d0; v1 *= d0; v2 *= d1; v3 *= d1;
            if (r0 < M) *(__half2*)(Cout + (size_t)r0 * 256 + col) = __floats2half2_rn(v0, v1);
            if (r1 < M) *(__half2*)(Cout + (size_t)r1 * 256 + col) = __floats2half2_rn(v2, v3);
        }
    }
}

// ---------------- CSR aggregate (fp16 gather, 4-way unrolled, fp16 h output) ----------------
__device__ __forceinline__ void acc_add(float* acc, uint4 v) {
    const __half2* p = (const __half2*)&v;
#pragma unroll
    for (int q = 0; q < 4; q++) {
        float2 f = __half22float2(p[q]);
        acc[2 * q] += f.x;
        acc[2 * q + 1] += f.y;
    }
}

__global__ void aggregate_h_k(const int* __restrict__ off, const int* __restrict__ adj,
                              const __half* __restrict__ g, const float* __restrict__ dinv,
                              const float* __restrict__ bias, __half* __restrict__ h) {
    int node = (blockIdx.x * blockDim.x + threadIdx.x) >> 5;
    if (node >= NNODES) return;
    int lane = threadIdx.x & 31;
    int col = lane << 3;

    float acc[8];
    {
        uint4 v = *(const uint4*)(g + (size_t)node * HID + col);
        const __half2* p = (const __half2*)&v;
#pragma unroll
        for (int q = 0; q < 4; q++) {
            float2 f = __half22float2(p[q]);
            acc[2 * q] = f.x;
            acc[2 * q + 1] = f.y;
        }
    }
    int e0 = off[node], e1 = off[node + 1];
    int j = e0;
    for (; j + 4 <= e1; j += 4) {
        int s0 = adj[j], s1 = adj[j + 1], s2 = adj[j + 2], s3 = adj[j + 3];
        uint4 v0 = *(const uint4*)(g + (size_t)s0 * HID + col);
        uint4 v1 = *(const uint4*)(g + (size_t)s1 * HID + col);
        uint4 v2 = *(const uint4*)(g + (size_t)s2 * HID + col);
        uint4 v3 = *(const uint4*)(g + (size_t)s3 * HID + col);
        acc_add(acc, v0);
        acc_add(acc, v1);
        acc_add(acc, v2);
        acc_add(acc, v3);
    }
    for (; j < e1; j++) {
        int s = adj[j];
        uint4 v = *(const uint4*)(g + (size_t)s * HID + col);
        acc_add(acc, v);
    }
    float dvv = dinv[node];
    uint32_t hp[4];
#pragma unroll
    for (int q = 0; q < 4; q++) {
        float o0 = fmaxf(fmaf(acc[2 * q], dvv, bias[col + 2 * q]), 0.0f);
        float o1 = fmaxf(fmaf(acc[2 * q + 1], dvv, bias[col + 2 * q + 1]), 0.0f);
        __half2 h2 = __floats2half2_rn(o0, o1);
        hp[q] = *(uint32_t*)&h2;
    }
    *(uint4*)(h + (size_t)node * HID + col) = make_uint4(hp[0], hp[1], hp[2], hp[3]);
}

// ---------------- pooling + head + output ----------------
__global__ void pool_partial_k(const __half* __restrict__ h, float* __restrict__ psum,
                               float* __restrict__ pmax) {
    int col = threadIdx.x;
    int b = blockIdx.x;
    float s = 0.0f, m = -1e30f;
    for (int r = b; r < NNODES; r += PB) {
        float v = __half2float(h[(size_t)r * HID + col]);
        s += v;
        m = fmaxf(m, v);
    }
    psum[b * HID + col] = s;
    pmax[b * HID + col] = m;
}

__global__ void head_k(const float* __restrict__ psum, const float* __restrict__ pmax,
                       const float* __restrict__ Wg1, const float* __restrict__ bg1,
                       const float* __restrict__ Wg2, const float* __restrict__ bg2,
                       const float* __restrict__ Wd1, const float* __restrict__ bd1,
                       const float* __restrict__ Wd2, const float* __restrict__ bd2,
                       float* __restrict__ out, float* __restrict__ prob) {
    __shared__ float rep[2 * HID];
    __shared__ float u1[HID];
    __shared__ float ge[EMB];
    __shared__ float v1[HID];
    __shared__ float vv[HID];
    __shared__ float red[HID];
    int t = threadIdx.x;

    if (t < HID) {
        float s = 0.0f;
        for (int i = 0; i < PB; i++) s += psum[i * HID + t];
        rep[t] = s * (1.0f / NNODES);
    } else {
        int c = t - HID;
        float m = -1e30f;
        for (int i = 0; i < PB; i++) m = fmaxf(m, pmax[i * HID + c]);
        rep[HID + c] = m;
    }
    __syncthreads();

    if (t < HID) {
        float s = bg1[t];
        for (int k = 0; k < 2 * HID; k++) s += rep[k] * Wg1[k * HID + t];
        u1[t] = fmaxf(s, 0.0f);
    }
    __syncthreads();

    if (t < EMB) {
        float s = bg2[t];
        for (int k = 0; k < HID; k++) s += u1[k] * Wg2[k * EMB + t];
        ge[t] = s;
        out[t] = s;
    }
    __syncthreads();

    if (t < HID) {
        float s = bd1[t];
        for (int k = 0; k < EMB; k++) s += ge[k] * Wd1[k * HID + t];
        v1[t] = fmaxf(s, 0.0f);
    }
    __syncthreads();

    if (t < HID) {
        float s = bd2[t];
        for (int k = 0; k < HID; k++) s += v1[k] * Wd2[k * HID + t];
        vv[t] = s;
    }
    __syncthreads();

    if (t < HID) red[t] = vv[t] * vv[t];
    __syncthreads();
    for (int s = HID / 2; s > 0; s >>= 1) {
        if (t < s) red[t] += red[t + s];
        __syncthreads();
    }
    if (t == 0) *prob = 1.0f / (1.0f + expf(-red[0]));
}

__global__ void fill_probs_k(float* __restrict__ out, const float* __restrict__ prob, int E) {
    int i = blockIdx.x * blockDim.x + threadIdx.x;
    float p = *prob;
    int base = i << 2;
    if (base + 3 < E) {
        *(float4*)(out + EMB + base) = make_float4(p, p, p, p);
    } else {
        for (int j = base; j < E; j++) out[EMB + j] = p;
    }
}

// ---------------- launch ----------------
extern "C" void kernel_launch(void* const* d_in, const int* in_sizes, int n_in,
                              void* d_out, int out_size) {
    const float* x = (const float*)d_in[0];
    const void* ei = d_in[1];
    const float* W1 = (const float*)d_in[2];
    const float* b1 = (const float*)d_in[3];
    const float* W2 = (const float*)d_in[4];
    const float* b2 = (const float*)d_in[5];
    const float* convW = (const float*)d_in[6];
    const float* convb = (const float*)d_in[7];
    const float* Wg1 = (const float*)d_in[8];
    const float* bg1 = (const float*)d_in[9];
    const float* Wg2 = (const float*)d_in[10];
    const float* bg2 = (const float*)d_in[11];
    const float* Wd1 = (const float*)d_in[12];
    const float* bd1 = (const float*)d_in[13];
    const float* Wd2 = (const float*)d_in[14];
    const float* bd2 = (const float*)d_in[15];

    int E = in_sizes[1] / 2;

    float *dinv, *psum, *pmax, *prob;
    __half *hh, *t1, *gh, *xh, *wt;
    int *src, *dst, *cnt, *cursor, *off, *adj, *bsum, *flag;
    cudaGetSymbolAddress((void**)&hh, g_hh);
    cudaGetSymbolAddress((void**)&t1, g_t1);
    cudaGetSymbolAddress((void**)&gh, g_gh);
    cudaGetSymbolAddress((void**)&xh, g_xh);
    cudaGetSymbolAddress((void**)&wt, g_wt);
    cudaGetSymbolAddress((void**)&dinv, g_dinv);
    cudaGetSymbolAddress((void**)&psum, g_psum);
    cudaGetSymbolAddress((void**)&pmax, g_pmax);
    cudaGetSymbolAddress((void**)&prob, g_prob);
    cudaGetSymbolAddress((void**)&src, g_src);
    cudaGetSymbolAddress((void**)&dst, g_dst);
    cudaGetSymbolAddress((void**)&cnt, g_cnt);
    cudaGetSymbolAddress((void**)&cursor, g_cursor);
    cudaGetSymbolAddress((void**)&off, g_off);
    cudaGetSymbolAddress((void**)&adj, g_adj);
    cudaGetSymbolAddress((void**)&bsum, g_bsum);
    cudaGetSymbolAddress((void**)&flag, g_flag);

    cudaFuncSetAttribute(gemm_h_k, cudaFuncAttributeMaxDynamicSharedMemorySize, GEMM_SMEM);

    dim3 ggrid(NB_M, 2);
    int prep_blocks = (XN + WT_TOTAL + 255) / 256;
    int agg_blocks = (NNODES * 32 + 255) / 256;

    // Fork a side stream for the CSR-build chain (independent of encoder GEMMs).
    // Handles intentionally leaked (destroying a capture-state stream is an error;
    // kernel_launch runs only a handful of times; no tracked device memory held).
    cudaStream_t s2;
    cudaStreamCreateWithFlags(&s2, cudaStreamNonBlocking);
    cudaEvent_t evF, evJ;
    cudaEventCreateWithFlags(&evF, cudaEventDisableTiming);
    cudaEventCreateWithFlags(&evJ, cudaEventDisableTiming);

    cudaEventRecord(evF, 0);
    cudaStreamWaitEvent(s2, evF, 0);

    // Branch B (stream s2): CSR build
    init_k<<<(NNODES + 255) / 256, 256, 0, s2>>>(flag, cnt, cursor);
    detect_k<<<16, 256, 0, s2>>>((const int*)ei, flag);
    convert_edges_k<<<(E + 255) / 256, 256, 0, s2>>>(ei, flag, src, dst, cnt, E);
    scanA_k<<<SCAN_B, 256, 0, s2>>>(cnt, bsum, dinv);
    scanB_k<<<SCAN_B, 256, 0, s2>>>(cnt, bsum, off);
    fill_k<<<(E + 255) / 256, 256, 0, s2>>>(src, dst, off, cursor, adj, E);
    cudaEventRecord(evJ, s2);

    // Branch A (main stream): prep + encoder GEMMs
    prep_k<<<prep_blocks, 256>>>(x, W1, W2, convW, xh, wt);
    gemm_h_k<<<ggrid, 256, GEMM_SMEM>>>(xh, wt, b1, t1, nullptr, NNODES, FIN, 1);
    gemm_h_k<<<ggrid, 256, GEMM_SMEM>>>(t1, wt + WT2_OFF, b2, hh, nullptr, NNODES, HID, 0);

    // Join: conv layers need dinv/off/adj (branch B) and hh (branch A)
    cudaStreamWaitEvent(0, evJ, 0);

    for (int l = 0; l < 3; l++) {
        gemm_h_k<<<ggrid, 256, GEMM_SMEM>>>(hh, wt + WTC_OFF + l * 65536, nullptr, gh,
                                            dinv, NNODES, HID, 0);
        aggregate_h_k<<<agg_blocks, 256>>>(off, adj, gh, dinv, convb + (size_t)l * HID, hh);
    }

    // pooling + head + output
    pool_partial_k<<<PB, 256>>>(hh, psum, pmax);
    head_k<<<1, 512>>>(psum, pmax, Wg1, bg1, Wg2, bg2, Wd1, bd1, Wd2, bd2, (float*)d_out, prob);
    fill_probs_k<<<(E / 4 + 255) / 256, 256>>>((float*)d_out, prob, E);
}

// round 16
// speedup vs baseline: 1.0682x; 1.0055x over previous
#include <cuda_runtime.h>
#include <cuda_fp16.h>
#include <math.h>
#include <stdint.h>

#define NNODES 50000
#define HID 256
#define EMB 128
#define FIN 64
#define EMAX 800000
#define PB 296
#define SCAN_B 196
#define NB_M 391  // ceil(50000/128)

#define XN (NNODES * FIN)
#define WT2_OFF 16384
#define WTC_OFF (16384 + 65536)
#define WT_TOTAL (WTC_OFF + 3 * 65536)

// ---- scratch (static device globals: no allocation allowed) ----
__device__ __half g_hh[NNODES * HID];   // node features (fp16)
__device__ __half g_t1[NNODES * HID];   // encoder intermediate
__device__ __half g_gh[NNODES * HID];   // per-layer g = dinv*(h@W)
__device__ __half g_xh[XN];             // x in fp16
__device__ __half g_wt[WT_TOTAL];       // transposed fp16 weights [N][K]
__device__ float g_dinv[NNODES];
__device__ float g_psum[PB * HID];
__device__ float g_pmax[PB * HID];
__device__ float g_prob;
__device__ int g_src[EMAX];
__device__ int g_dst[EMAX];
__device__ int g_cnt[NNODES];
__device__ int g_cursor[NNODES];
__device__ int g_off[NNODES + 1];
__device__ int g_adj[EMAX];
__device__ int g_bsum[SCAN_B];
__device__ int g_flag;

// ---------------- helpers ----------------
__device__ __forceinline__ uint32_t smem_u32(const void* p) {
    uint32_t a;
    asm("{ .reg .u64 t; cvta.to.shared.u64 t, %1; cvt.u32.u64 %0, t; }" : "=r"(a) : "l"(p));
    return a;
}

__device__ __forceinline__ void cp_async16(void* smem_dst, const void* gsrc, bool pred) {
    uint32_t s = (uint32_t)__cvta_generic_to_shared(smem_dst);
    int sz = pred ? 16 : 0;
    asm volatile("cp.async.cg.shared.global [%0], [%1], 16, %2;\n" :: "r"(s), "l"(gsrc), "r"(sz));
}

__device__ __forceinline__ void ldm_x4(uint32_t& r0, uint32_t& r1, uint32_t& r2, uint32_t& r3,
                                       uint32_t addr) {
    asm volatile("ldmatrix.sync.aligned.m8n8.x4.shared.b16 {%0,%1,%2,%3}, [%4];"
                 : "=r"(r0), "=r"(r1), "=r"(r2), "=r"(r3) : "r"(addr));
}

// ---------------- setup kernels ----------------
__global__ void init_k(int* flag, int* cnt, int* cursor) {
    int i = blockIdx.x * blockDim.x + threadIdx.x;
    if (i == 0) *flag = 1;
    if (i < NNODES) { cnt[i] = 0; cursor[i] = 0; }
}

// prep: xh = fp16(x); wt = fp16(transpose(W1,W2,convW)) into [N,K] K-major
__global__ void prep_k(const float* __restrict__ x, const float* __restrict__ W1,
                       const float* __restrict__ W2, const float* __restrict__ convW,
                       __half* __restrict__ xh, __half* __restrict__ wt) {
    int i = blockIdx.x * blockDim.x + threadIdx.x;
    if (i < XN) { xh[i] = __float2half_rn(x[i]); return; }
    int j = i - XN;
    if (j < 16384) {  // Wt1[n][k], k<64
        int n = j >> 6, k = j & 63;
        wt[j] = __float2half_rn(W1[k * 256 + n]);
        return;
    }
    j -= 16384;
    if (j < 65536) {  // Wt2[n][k]
        int n = j >> 8, k = j & 255;
        wt[WT2_OFF + j] = __float2half_rn(W2[k * 256 + n]);
        return;
    }
    j -= 65536;
    if (j < 3 * 65536) {
        int l = j >> 16;
        int r = j & 65535;
        int n = r >> 8, k = r & 255;
        wt[WTC_OFF + j] = __float2half_rn(convW[l * 65536 + k * 256 + n]);
    }
}

__global__ void detect_k(const int* p, int* flag) {
    int i = blockIdx.x * blockDim.x + threadIdx.x;
    if (p[2 * i + 1] != 0) *flag = 0;
}

__global__ void convert_edges_k(const void* ei, const int* flag, int* src, int* dst,
                                int* cnt, int E) {
    int i = blockIdx.x * blockDim.x + threadIdx.x;
    if (i >= E) return;
    int s, d;
    if (*flag) {
        const long long* p = (const long long*)ei;
        s = (int)p[i];
        d = (int)p[E + i];
    } else {
        const int* p = (const int*)ei;
        s = p[i];
        d = p[E + i];
    }
    src[i] = s;
    dst[i] = d;
    atomicAdd(&cnt[d], 1);
}

__global__ void scanA_k(const int* __restrict__ cnt, int* __restrict__ bsum,
                        float* __restrict__ dinv) {
    __shared__ int s[256];
    int t = threadIdx.x;
    int i = blockIdx.x * 256 + t;
    int v = (i < NNODES) ? cnt[i] : 0;
    if (i < NNODES) dinv[i] = rsqrtf((float)v + 1.0f);
    s[t] = v;
    __syncthreads();
    for (int d = 128; d > 0; d >>= 1) {
        if (t < d) s[t] += s[t + d];
        __syncthreads();
    }
    if (t == 0) bsum[blockIdx.x] = s[0];
}

__global__ void scanB_k(const int* __restrict__ cnt, const int* __restrict__ bsum,
                        int* __restrict__ off) {
    __shared__ int s[256];
    __shared__ int red[256];
    int t = threadIdx.x;
    int b = blockIdx.x;
    int i = b * 256 + t;
    int val = (i < NNODES) ? cnt[i] : 0;
    int partial = 0;
    for (int j = t; j < b; j += 256) partial += bsum[j];
    red[t] = partial;
    __syncthreads();
    for (int d = 128; d > 0; d >>= 1) {
        if (t < d) red[t] += red[t + d];
        __syncthreads();
    }
    int base = red[0];
    s[t] = val;
    __syncthreads();
    for (int d = 1; d < 256; d <<= 1) {
        int tmp = (t >= d) ? s[t - d] : 0;
        __syncthreads();
        s[t] += tmp;
        __syncthreads();
    }
    if (i <= NNODES) off[i] = base + s[t] - val;
}

__global__ void fill_k(const int* __restrict__ src, const int* __restrict__ dst,
                       const int* __restrict__ off, int* __restrict__ cursor,
                       int* __restrict__ adj, int E) {
    int i = blockIdx.x * blockDim.x + threadIdx.x;
    if (i >= E) return;
    int d = dst[i];
    int p = atomicAdd(&cursor[d], 1);
    adj[off[d] + p] = src[i];
}

// ---------------- FP16 tensor-core GEMM (mma.m16n8k16 + ldmatrix) ----------------
// Block tile 128x256 (full N), warp tile 32x128, grid (NB_M, 1), 1 CTA/SM.
// Per k16 per warp: 2 A-ldmatrix + 8 B-ldmatrix -> 32 mma (ratio 0.31 vs 0.375).
// Single __syncthreads per k-tile (NSTAGE=3, prefetch issued after the barrier).
#define A_TILE_BYTES 16384               // 128 x 128B
#define B_TILE_BYTES 32768               // 256 x 128B
#define STAGE_BYTES (A_TILE_BYTES + B_TILE_BYTES)
#define NSTAGE 3
#define GEMM_SMEM (NSTAGE * STAGE_BYTES) // 147456

__global__ __launch_bounds__(256, 1) void gemm_h_k(
    const __half* __restrict__ A, const __half* __restrict__ Bt,
    const float* __restrict__ bias, __half* __restrict__ Cout,
    const float* __restrict__ dinvv, int M, int K, int relu_flag) {
    extern __shared__ char smem[];
    uint32_t sb = smem_u32(smem);

    int tid = threadIdx.x;
    int warp = tid >> 5;
    int lane = tid & 31;
    int grp = lane >> 2;   // 0..7
    int tig = lane & 3;    // 0..3
    int wm = warp >> 1;    // 0..3 -> m offset wm*32
    int wn = warp & 1;     // 0..1 -> n offset wn*128
    int bm = blockIdx.x * 128;
    int ntiles = K >> 6;

    float c[2][16][4];
#pragma unroll
    for (int mt = 0; mt < 2; mt++)
#pragma unroll
        for (int nt = 0; nt < 16; nt++)
#pragma unroll
            for (int q = 0; q < 4; q++) c[mt][nt][q] = 0.0f;

    auto stage = [&](int t) {
        char* As = smem + (t % NSTAGE) * STAGE_BYTES;
        char* Bs = As + A_TILE_BYTES;
        int k0 = t << 6;
        // A: 128 rows x 8 chunks = 1024 cp16 (4/thread)
#pragma unroll
        for (int i = 0; i < 4; i++) {
            int ci = tid + i * 256;
            int row = ci >> 3;
            int ch = ci & 7;
            uint32_t sw = (uint32_t)(row * 128 + ((ch ^ (row & 7)) << 4));
            int gm = bm + row;
            bool ok = gm < M;
            int gms = ok ? gm : 0;
            cp_async16(As + sw, A + (size_t)gms * K + k0 + ch * 8, ok);
        }
        // B: 256 rows x 8 chunks = 2048 cp16 (8/thread)
#pragma unroll
        for (int i = 0; i < 8; i++) {
            int ci = tid + i * 256;
            int row = ci >> 3;
            int ch = ci & 7;
            uint32_t sw = (uint32_t)(row * 128 + ((ch ^ (row & 7)) << 4));
            cp_async16(Bs + sw, Bt + (size_t)row * K + k0 + ch * 8, true);
        }
        asm volatile("cp.async.commit_group;\n");
    };

    stage(0);
    if (ntiles > 1) stage(1);

    for (int t = 0; t < ntiles; t++) {
        int commits = (ntiles < t + 2) ? ntiles : (t + 2);
        int pend = commits - t - 1;  // 0 or 1
        if (pend >= 1) asm volatile("cp.async.wait_group 1;\n");
        else asm volatile("cp.async.wait_group 0;\n");
        __syncthreads();
        if (t + 2 < ntiles) stage(t + 2);

        uint32_t as_b = sb + (t % NSTAGE) * STAGE_BYTES;
        uint32_t bs_b = as_b + A_TILE_BYTES;

#pragma unroll
        for (int ks = 0; ks < 4; ks++) {
            int kc0 = ks << 1;
            uint32_t a[2][4];
#pragma unroll
            for (int mt = 0; mt < 2; mt++) {
                int row = wm * 32 + mt * 16 + (lane & 7) + (lane & 8);
                int ch = kc0 + (lane >> 4);
                uint32_t addr = as_b + (uint32_t)(row * 128 + ((ch ^ (row & 7)) << 4));
                ldm_x4(a[mt][0], a[mt][1], a[mt][2], a[mt][3], addr);
            }
            uint32_t b[16][2];
#pragma unroll
            for (int p = 0; p < 8; p++) {
                int nrow = wn * 128 + p * 16 + (lane & 7) + ((lane & 16) >> 1);
                int ch = kc0 + ((lane >> 3) & 1);
                uint32_t addr = bs_b + (uint32_t)(nrow * 128 + ((ch ^ (nrow & 7)) << 4));
                uint32_t r0, r1, r2, r3;
                ldm_x4(r0, r1, r2, r3, addr);
                b[2 * p][0] = r0; b[2 * p][1] = r1;
                b[2 * p + 1][0] = r2; b[2 * p + 1][1] = r3;
            }
#pragma unroll
            for (int mt = 0; mt < 2; mt++)
#pragma unroll
                for (int nt = 0; nt < 16; nt++) {
                    asm volatile(
                        "mma.sync.aligned.m16n8k16.row.col.f32.f16.f16.f32 "
                        "{%0,%1,%2,%3},{%4,%5,%6,%7},{%8,%9},{%0,%1,%2,%3};\n"
                        : "+f"(c[mt][nt][0]), "+f"(c[mt][nt][1]),
                          "+f"(c[mt][nt][2]), "+f"(c[mt][nt][3])
                        : "r"(a[mt][0]), "r"(a[mt][1]), "r"(a[mt][2]), "r"(a[mt][3]),
                          "r"(b[nt][0]), "r"(b[nt][1]));
                }
        }
    }

    // epilogue
#pragma unroll
    for (int mt = 0; mt < 2; mt++) {
        int r0 = bm + wm * 32 + mt * 16 + grp;
        int r1 = r0 + 8;
        float d0 = 1.0f, d1 = 1.0f;
        if (dinvv) {
            if (r0 < M) d0 = dinvv[r0];
            if (r1 < M) d1 = dinvv[r1];
        }
#pragma unroll
        for (int nt = 0; nt < 16; nt++) {
            int col = wn * 128 + nt * 8 + 2 * tig;
            float b0f = 0.f, b1f = 0.f;
            if (bias) { b0f = bias[col]; b1f = bias[col + 1]; }
            float v0 = c[mt][nt][0] + b0f;
            float v1 = c[mt][nt][1] + b1f;
            float v2 = c[mt][nt][2] + b0f;
            float v3 = c[mt][nt][3] + b1f;
            if (relu_flag) {
                v0 = fmaxf(v0, 0.f); v1 = fmaxf(v1, 0.f);
                v2 = fmaxf(v2, 0.f); v3 = fmaxf(v3, 0.f);
            }
            v0 *= d0; v1 *= d0; v2 *= d1; v3 *= d1;
            if (r0 < M) *(__half2*)(Cout + (size_t)r0 * 256 + col) = __floats2half2_rn(v0, v1);
            if (r1 < M) *(__half2*)(Cout + (size_t)r1 * 256 + col) = __floats2half2_rn(v2, v3);
        }
    }
}

// ---------------- CSR aggregate (fp16 gather, 4-way unrolled, fp16 h output) ----------------
__device__ __forceinline__ void acc_add(float* acc, uint4 v) {
    const __half2* p = (const __half2*)&v;
#pragma unroll
    for (int q = 0; q < 4; q++) {
        float2 f = __half22float2(p[q]);
        acc[2 * q] += f.x;
        acc[2 * q + 1] += f.y;
    }
}

__global__ void aggregate_h_k(const int* __restrict__ off, const int* __restrict__ adj,
                              const __half* __restrict__ g, const float* __restrict__ dinv,
                              const float* __restrict__ bias, __half* __restrict__ h) {
    int node = (blockIdx.x * blockDim.x + threadIdx.x) >> 5;
    if (node >= NNODES) return;
    int lane = threadIdx.x & 31;
    int col = lane << 3;

    float acc[8];
    {
        uint4 v = *(const uint4*)(g + (size_t)node * HID + col);
        const __half2* p = (const __half2*)&v;
#pragma unroll
        for (int q = 0; q < 4; q++) {
            float2 f = __half22float2(p[q]);
            acc[2 * q] = f.x;
            acc[2 * q + 1] = f.y;
        }
    }
    int e0 = off[node], e1 = off[node + 1];
    int j = e0;
    for (; j + 4 <= e1; j += 4) {
        int s0 = adj[j], s1 = adj[j + 1], s2 = adj[j + 2], s3 = adj[j + 3];
        uint4 v0 = *(const uint4*)(g + (size_t)s0 * HID + col);
        uint4 v1 = *(const uint4*)(g + (size_t)s1 * HID + col);
        uint4 v2 = *(const uint4*)(g + (size_t)s2 * HID + col);
        uint4 v3 = *(const uint4*)(g + (size_t)s3 * HID + col);
        acc_add(acc, v0);
        acc_add(acc, v1);
        acc_add(acc, v2);
        acc_add(acc, v3);
    }
    for (; j < e1; j++) {
        int s = adj[j];
        uint4 v = *(const uint4*)(g + (size_t)s * HID + col);
        acc_add(acc, v);
    }
    float dvv = dinv[node];
    uint32_t hp[4];
#pragma unroll
    for (int q = 0; q < 4; q++) {
        float o0 = fmaxf(fmaf(acc[2 * q], dvv, bias[col + 2 * q]), 0.0f);
        float o1 = fmaxf(fmaf(acc[2 * q + 1], dvv, bias[col + 2 * q + 1]), 0.0f);
        __half2 h2 = __floats2half2_rn(o0, o1);
        hp[q] = *(uint32_t*)&h2;
    }
    *(uint4*)(h + (size_t)node * HID + col) = make_uint4(hp[0], hp[1], hp[2], hp[3]);
}

// ---------------- pooling + head + output ----------------
__global__ void pool_partial_k(const __half* __restrict__ h, float* __restrict__ psum,
                               float* __restrict__ pmax) {
    int col = threadIdx.x;
    int b = blockIdx.x;
    float s = 0.0f, m = -1e30f;
    for (int r = b; r < NNODES; r += PB) {
        float v = __half2float(h[(size_t)r * HID + col]);
        s += v;
        m = fmaxf(m, v);
    }
    psum[b * HID + col] = s;
    pmax[b * HID + col] = m;
}

__global__ void head_k(const float* __restrict__ psum, const float* __restrict__ pmax,
                       const float* __restrict__ Wg1, const float* __restrict__ bg1,
                       const float* __restrict__ Wg2, const float* __restrict__ bg2,
                       const float* __restrict__ Wd1, const float* __restrict__ bd1,
                       const float* __restrict__ Wd2, const float* __restrict__ bd2,
                       float* __restrict__ out, float* __restrict__ prob) {
    __shared__ float rep[2 * HID];
    __shared__ float u1[HID];
    __shared__ float ge[EMB];
    __shared__ float v1[HID];
    __shared__ float vv[HID];
    __shared__ float red[HID];
    int t = threadIdx.x;

    if (t < HID) {
        float s = 0.0f;
        for (int i = 0; i < PB; i++) s += psum[i * HID + t];
        rep[t] = s * (1.0f / NNODES);
    } else {
        int c = t - HID;
        float m = -1e30f;
        for (int i = 0; i < PB; i++) m = fmaxf(m, pmax[i * HID + c]);
        rep[HID + c] = m;
    }
    __syncthreads();

    if (t < HID) {
        float s = bg1[t];
        for (int k = 0; k < 2 * HID; k++) s += rep[k] * Wg1[k * HID + t];
        u1[t] = fmaxf(s, 0.0f);
    }
    __syncthreads();

    if (t < EMB) {
        float s = bg2[t];
        for (int k = 0; k < HID; k++) s += u1[k] * Wg2[k * EMB + t];
        ge[t] = s;
        out[t] = s;
    }
    __syncthreads();

    if (t < HID) {
        float s = bd1[t];
        for (int k = 0; k < EMB; k++) s += ge[k] * Wd1[k * HID + t];
        v1[t] = fmaxf(s, 0.0f);
    }
    __syncthreads();

    if (t < HID) {
        float s = bd2[t];
        for (int k = 0; k < HID; k++) s += v1[k] * Wd2[k * HID + t];
        vv[t] = s;
    }
    __syncthreads();

    if (t < HID) red[t] = vv[t] * vv[t];
    __syncthreads();
    for (int s = HID / 2; s > 0; s >>= 1) {
        if (t < s) red[t] += red[t + s];
        __syncthreads();
    }
    if (t == 0) *prob = 1.0f / (1.0f + expf(-red[0]));
}

__global__ void fill_probs_k(float* __restrict__ out, const float* __restrict__ prob, int E) {
    int i = blockIdx.x * blockDim.x + threadIdx.x;
    float p = *prob;
    int base = i << 2;
    if (base + 3 < E) {
        *(float4*)(out + EMB + base) = make_float4(p, p, p, p);
    } else {
        for (int j = base; j < E; j++) out[EMB + j] = p;
    }
}

// ---------------- launch ----------------
extern "C" void kernel_launch(void* const* d_in, const int* in_sizes, int n_in,
                              void* d_out, int out_size) {
    const float* x = (const float*)d_in[0];
    const void* ei = d_in[1];
    const float* W1 = (const float*)d_in[2];
    const float* b1 = (const float*)d_in[3];
    const float* W2 = (const float*)d_in[4];
    const float* b2 = (const float*)d_in[5];
    const float* convW = (const float*)d_in[6];
    const float* convb = (const float*)d_in[7];
    const float* Wg1 = (const float*)d_in[8];
    const float* bg1 = (const float*)d_in[9];
    const float* Wg2 = (const float*)d_in[10];
    const float* bg2 = (const float*)d_in[11];
    const float* Wd1 = (const float*)d_in[12];
    const float* bd1 = (const float*)d_in[13];
    const float* Wd2 = (const float*)d_in[14];
    const float* bd2 = (const float*)d_in[15];

    int E = in_sizes[1] / 2;

    float *dinv, *psum, *pmax, *prob;
    __half *hh, *t1, *gh, *xh, *wt;
    int *src, *dst, *cnt, *cursor, *off, *adj, *bsum, *flag;
    cudaGetSymbolAddress((void**)&hh, g_hh);
    cudaGetSymbolAddress((void**)&t1, g_t1);
    cudaGetSymbolAddress((void**)&gh, g_gh);
    cudaGetSymbolAddress((void**)&xh, g_xh);
    cudaGetSymbolAddress((void**)&wt, g_wt);
    cudaGetSymbolAddress((void**)&dinv, g_dinv);
    cudaGetSymbolAddress((void**)&psum, g_psum);
    cudaGetSymbolAddress((void**)&pmax, g_pmax);
    cudaGetSymbolAddress((void**)&prob, g_prob);
    cudaGetSymbolAddress((void**)&src, g_src);
    cudaGetSymbolAddress((void**)&dst, g_dst);
    cudaGetSymbolAddress((void**)&cnt, g_cnt);
    cudaGetSymbolAddress((void**)&cursor, g_cursor);
    cudaGetSymbolAddress((void**)&off, g_off);
    cudaGetSymbolAddress((void**)&adj, g_adj);
    cudaGetSymbolAddress((void**)&bsum, g_bsum);
    cudaGetSymbolAddress((void**)&flag, g_flag);

    cudaFuncSetAttribute(gemm_h_k, cudaFuncAttributeMaxDynamicSharedMemorySize, GEMM_SMEM);

    dim3 ggrid(NB_M, 1);
    int prep_blocks = (XN + WT_TOTAL + 255) / 256;
    int agg_blocks = (NNODES * 32 + 255) / 256;

    // Fork a side stream for the CSR-build chain (independent of encoder GEMMs).
    // Handles intentionally leaked (destroying a capture-state stream is an error;
    // kernel_launch runs only a handful of times; no tracked device memory held).
    cudaStream_t s2;
    cudaStreamCreateWithFlags(&s2, cudaStreamNonBlocking);
    cudaEvent_t evF, evJ;
    cudaEventCreateWithFlags(&evF, cudaEventDisableTiming);
    cudaEventCreateWithFlags(&evJ, cudaEventDisableTiming);

    cudaEventRecord(evF, 0);
    cudaStreamWaitEvent(s2, evF, 0);

    // Branch B (stream s2): CSR build
    init_k<<<(NNODES + 255) / 256, 256, 0, s2>>>(flag, cnt, cursor);
    detect_k<<<16, 256, 0, s2>>>((const int*)ei, flag);
    convert_edges_k<<<(E + 255) / 256, 256, 0, s2>>>(ei, flag, src, dst, cnt, E);
    scanA_k<<<SCAN_B, 256, 0, s2>>>(cnt, bsum, dinv);
    scanB_k<<<SCAN_B, 256, 0, s2>>>(cnt, bsum, off);
    fill_k<<<(E + 255) / 256, 256, 0, s2>>>(src, dst, off, cursor, adj, E);
    cudaEventRecord(evJ, s2);

    // Branch A (main stream): prep + encoder GEMMs
    prep_k<<<prep_blocks, 256>>>(x, W1, W2, convW, xh, wt);
    gemm_h_k<<<ggrid, 256, GEMM_SMEM>>>(xh, wt, b1, t1, nullptr, NNODES, FIN, 1);
    gemm_h_k<<<ggrid, 256, GEMM_SMEM>>>(t1, wt + WT2_OFF, b2, hh, nullptr, NNODES, HID, 0);

    // Join: conv layers need dinv/off/adj (branch B) and hh (branch A)
    cudaStreamWaitEvent(0, evJ, 0);

    for (int l = 0; l < 3; l++) {
        gemm_h_k<<<ggrid, 256, GEMM_SMEM>>>(hh, wt + WTC_OFF + l * 65536, nullptr, gh,
                                            dinv, NNODES, HID, 0);
        aggregate_h_k<<<agg_blocks, 256>>>(off, adj, gh, dinv, convb + (size_t)l * HID, hh);
    }

    // pooling + head + output
    pool_partial_k<<<PB, 256>>>(hh, psum, pmax);
    head_k<<<1, 512>>>(psum, pmax, Wg1, bg1, Wg2, bg2, Wd1, bd1, Wd2, bd2, (float*)d_out, prob);
    fill_probs_k<<<(E / 4 + 255) / 256, 256>>>((float*)d_out, prob, E);
}